// round 8
// baseline (speedup 1.0000x reference)
#include <cuda_runtime.h>

// ---------------------------------------------------------------------------
// GRU (511 steps) + BCE loss. Persistent, 256 CTAs (16 batch x 16 unit
// groups), 2 CTAs/SM. CTA: 16 rows x 16 units (48 gate rows), K=384 as 8
// interleaved slices [32 h | 16 x | 4 pad] (SLICE_F=52).
// Warp = (unit-quad uh, K-half kc); lane = rg*4 + ksl (slice = kc*4+ksl).
// Thread: 2 rows x 4 units x 3 gates x 48k, fma.rn.f32x2.
// Reduction: shfl over ksl, smem exchange over kc (reusing sA x-region).
// ---------------------------------------------------------------------------

#define BATCH 256
#define IN_DIM 128
#define HID 256
#define STEPS 511
#define NCTA 256
#define NTHREADS 256
#define SLICE_F 52
#define ROW_F 416
#define ROW_Q 104                        // ulonglong2 per row
#define SLICE_Q 13

#define OFF_W 0                          // 48 gate-rows x ROW_F
#define OFF_A (48 * ROW_F)               // 19968
#define OFF_SB (OFF_A + 16 * ROW_F)      // 26624
#define OFF_WD (OFF_SB + 64)             // 26688
#define SMEM_FLOATS (OFF_WD + 256)       // 26944
#define SMEM_BYTES (SMEM_FLOATS * 4)     // 107776

typedef unsigned long long u64;

__device__ float    g_h[2][BATCH * HID];
__device__ unsigned g_arr[16 * 32];

__global__ void gru_init_kernel(float* out) {
    int i = blockIdx.x * blockDim.x + threadIdx.x;
    if (i == 0) out[0] = 0.0f;
    if (i < 16 * 32) g_arr[i] = 0u;
    for (int j = i; j < BATCH * HID; j += gridDim.x * blockDim.x)
        g_h[0][j] = 0.0f;
}

__device__ __forceinline__ u64 ffma2(u64 a, u64 b, u64 c) {
    u64 d;
    asm("fma.rn.f32x2 %0, %1, %2, %3;" : "=l"(d) : "l"(a), "l"(b), "l"(c));
    return d;
}
__device__ __forceinline__ u64 addf2(u64 a, u64 b) {
    u64 d;
    asm("add.rn.f32x2 %0, %1, %2;" : "=l"(d) : "l"(a), "l"(b));
    return d;
}
__device__ __forceinline__ float sum2(u64 u) {
    return __uint_as_float((unsigned)u) + __uint_as_float((unsigned)(u >> 32));
}
__device__ __forceinline__ float sigf(float v) { return 1.0f / (1.0f + __expf(-v)); }
__device__ __forceinline__ unsigned ld_acq(const unsigned* p) {
    unsigned v;
    asm volatile("ld.acquire.gpu.global.u32 %0, [%1];" : "=r"(v) : "l"(p) : "memory");
    return v;
}

__global__ __launch_bounds__(NTHREADS, 2)
void gru_main_kernel(const float* __restrict__ x, const float* __restrict__ gt,
                     const float* __restrict__ W_ih, const float* __restrict__ W_hh,
                     const float* __restrict__ b_ih, const float* __restrict__ b_hh,
                     const float* __restrict__ W_dec, const float* __restrict__ b_dec,
                     float* __restrict__ out)
{
    extern __shared__ float smem[];
    float* sW  = smem + OFF_W;
    float* sA  = smem + OFF_A;
    float* sb  = smem + OFF_SB;
    float* sWd = smem + OFF_WD;

    const int tid = threadIdx.x;
    const int cb  = blockIdx.x & 15;
    const int cu  = blockIdx.x >> 4;
    const int B0  = cb * 16;
    const int U0  = cu * 16;

    const int lane = tid & 31;
    const int wrp  = tid >> 5;
    const int kc   = wrp & 1;            // K-half (slices 0-3 vs 4-7)
    const int uh   = wrp >> 1;           // unit-quad: units 4uh..4uh+3
    const int ksl  = lane & 3;           // K-quarter within half
    const int rg   = lane >> 2;          // row-group: rows 2rg, 2rg+1
    const int sl   = kc * 4 + ksl;       // slice 0..7 (48 used floats)

    // ---- persistent W (48 gate-rows x 384 k, interleaved slices) + biases
    for (int idx = tid; idx < 48 * 384; idx += NTHREADS) {
        int gr = idx / 384, k = idx - gr * 384;
        int g = gr >> 4, uu = gr & 15, wrow = g * HID + U0 + uu;
        int s, o; float v;
        if (k < HID) { s = k >> 5; o = k & 31; v = W_hh[wrow * HID + k]; }
        else { int kx = k - HID; s = kx >> 4; o = 32 + (kx & 15); v = W_ih[wrow * IN_DIM + kx]; }
        sW[gr * ROW_F + s * SLICE_F + o] = v;
    }
    if (tid < 16) {
        sb[tid]      = b_ih[U0 + tid] + b_hh[U0 + tid];
        sb[16 + tid] = b_ih[HID + U0 + tid] + b_hh[HID + U0 + tid];
        sb[32 + tid] = b_ih[2 * HID + U0 + tid];
        sb[48 + tid] = b_hh[2 * HID + U0 + tid];
    }
    sWd[tid] = W_dec[tid];
    __syncthreads();

    const float bdec = b_dec[0];
    float loss_local = 0.0f;
    int p = 0;

    const ulonglong2* Ab = (const ulonglong2*)sA + (2 * rg) * ROW_Q + sl * SLICE_Q;
    const ulonglong2* Wb = (const ulonglong2*)sW + (4 * uh) * ROW_Q + sl * SLICE_Q;
    // cross-kc exchange buffer: this thread's 16-float block in sA's x-region
    u64* xb = (u64*)(sA + (uh * 4 + (lane >> 3)) * ROW_F + (lane & 7) * SLICE_F + 32);
    const unsigned* cnt = &g_arr[cb * 32];

    const int p0 = ksl & 1, p1 = ksl >> 1;

    for (int t = 0; t < STEPS; ++t) {
        u64 acc[4][4][2];                 // [r,z,nh,ni][unit j][row]
        #pragma unroll
        for (int q = 0; q < 4; ++q)
            #pragma unroll
            for (int j = 0; j < 4; ++j)
                { acc[q][j][0] = 0ull; acc[q][j][1] = 0ull; }

        // ---- stage x(t) into slice x-regions
        {
            int row = tid >> 4;
            const float4* src = (const float4*)(x + ((size_t)t * BATCH + B0 + row) * IN_DIM);
            #pragma unroll
            for (int q = 0; q < 2; ++q) {
                int idx = (tid & 15) + 16 * q;
                float4 v = __ldg(src + idx);
                *(float4*)(sA + row * ROW_F + (idx >> 2) * SLICE_F + 32 + 4 * (idx & 3)) = v;
            }
        }
        __syncthreads();

        #define GSTEP(I, NQ) {                                             \
            ulonglong2 a0 = Ab[I], a1 = Ab[ROW_Q + (I)];                   \
            _Pragma("unroll")                                              \
            for (int j = 0; j < 4; ++j) {                                  \
                ulonglong2 wr = Wb[(j)      * ROW_Q + (I)];                \
                ulonglong2 wz = Wb[(16 + j) * ROW_Q + (I)];                \
                ulonglong2 wn = Wb[(32 + j) * ROW_Q + (I)];                \
                acc[0][j][0] = ffma2(a0.x, wr.x, acc[0][j][0]);            \
                acc[0][j][0] = ffma2(a0.y, wr.y, acc[0][j][0]);            \
                acc[0][j][1] = ffma2(a1.x, wr.x, acc[0][j][1]);            \
                acc[0][j][1] = ffma2(a1.y, wr.y, acc[0][j][1]);            \
                acc[1][j][0] = ffma2(a0.x, wz.x, acc[1][j][0]);            \
                acc[1][j][0] = ffma2(a0.y, wz.y, acc[1][j][0]);            \
                acc[1][j][1] = ffma2(a1.x, wz.x, acc[1][j][1]);            \
                acc[1][j][1] = ffma2(a1.y, wz.y, acc[1][j][1]);            \
                acc[NQ][j][0] = ffma2(a0.x, wn.x, acc[NQ][j][0]);          \
                acc[NQ][j][0] = ffma2(a0.y, wn.y, acc[NQ][j][0]);          \
                acc[NQ][j][1] = ffma2(a1.x, wn.x, acc[NQ][j][1]);          \
                acc[NQ][j][1] = ffma2(a1.y, wn.y, acc[NQ][j][1]); } }

        // ---- x-part GEMM (quads 8..11) before the barrier wait
        #pragma unroll
        for (int i = 8; i < 12; ++i) GSTEP(i, 3)

        // ---- wait for h(t)
        if (t > 0) {
            if (tid == 0) {
                unsigned target = (unsigned)t * 16u;
                while (ld_acq(cnt) < target) __nanosleep(20);
            }
            __syncthreads();
        }

        // ---- stage h(t)
        {
            int row = tid >> 4;
            const float4* src = (const float4*)(g_h[p] + (B0 + row) * HID);
            #pragma unroll
            for (int q = 0; q < 4; ++q) {
                int idx = (tid & 15) + 16 * q;
                float4 v = __ldcg(src + idx);
                *(float4*)(sA + row * ROW_F + (idx >> 3) * SLICE_F + 4 * (idx & 7)) = v;
            }
        }
        __syncthreads();

        // ---- loss for h(t) (row B0+cu), warp 0
        if (tid < 32 && t > 0) {
            float s = 0.0f;
            #pragma unroll
            for (int q = 0; q < 8; ++q)
                s += sA[cu * ROW_F + q * SLICE_F + lane] * sWd[q * 32 + lane];
            #pragma unroll
            for (int sft = 16; sft > 0; sft >>= 1)
                s += __shfl_down_sync(0xffffffffu, s, sft);
            if (lane == 0) {
                float l = s + bdec;
                float g = gt[t * BATCH + B0 + cu];
                loss_local += fmaxf(l, 0.0f) + log1pf(__expf(-fabsf(l))) - g * l;
            }
        }

        // ---- h-part GEMM (quads 0..7)
        #pragma unroll
        for (int i = 0; i < 8; ++i) GSTEP(i, 2)
        #undef GSTEP

        // ---- reduce over ksl: level 1 (xor 2) keeps unit-pair p1
        u64 t1[4][2][2];
        #pragma unroll
        for (int q = 0; q < 4; ++q)
            #pragma unroll
            for (int jj = 0; jj < 2; ++jj)
                #pragma unroll
                for (int r = 0; r < 2; ++r) {
                    u64 snd = p1 ? acc[q][jj][r] : acc[q][2 + jj][r];
                    u64 rcv = __shfl_xor_sync(0xffffffffu, snd, 2);
                    u64 kp  = p1 ? acc[q][2 + jj][r] : acc[q][jj][r];
                    t1[q][jj][r] = addf2(kp, rcv);
                }
        // level 2 (xor 1) keeps row p0
        u64 fin[4][2];
        #pragma unroll
        for (int q = 0; q < 4; ++q)
            #pragma unroll
            for (int jj = 0; jj < 2; ++jj) {
                u64 snd = p0 ? t1[q][jj][0] : t1[q][jj][1];
                u64 rcv = __shfl_xor_sync(0xffffffffu, snd, 1);
                u64 kp  = p0 ? t1[q][jj][1] : t1[q][jj][0];
                fin[q][jj] = addf2(kp, rcv);
            }

        // ---- cross-kc exchange through sA's (dead) x-region
        if (kc == 1) {
            #pragma unroll
            for (int q = 0; q < 4; ++q)
                #pragma unroll
                for (int jj = 0; jj < 2; ++jj) xb[q * 2 + jj] = fin[q][jj];
        }
        __syncthreads();

        // ---- epilogue (kc==0): 2 h elements per thread
        if (kc == 0) {
            int row = 2 * rg + p0;
            #pragma unroll
            for (int jj = 0; jj < 2; ++jj) {
                int un = 4 * uh + 2 * p1 + jj;
                float rr = sum2(fin[0][jj]) + sum2(xb[jj]);
                float zz = sum2(fin[1][jj]) + sum2(xb[2 + jj]);
                float hh = sum2(fin[2][jj]) + sum2(xb[4 + jj]);
                float ii = sum2(fin[3][jj]) + sum2(xb[6 + jj]);
                float rv = sigf(rr + sb[un]);
                float zv = sigf(zz + sb[16 + un]);
                float pre = ii + sb[32 + un] + rv * (hh + sb[48 + un]);
                float nv = 2.0f * sigf(2.0f * pre) - 1.0f;       // tanh
                int kcol = U0 + un;
                float hp = sA[row * ROW_F + (kcol >> 5) * SLICE_F + (kcol & 31)];
                float hn = nv + zv * (hp - nv);
                g_h[p ^ 1][(B0 + row) * HID + kcol] = hn;
            }
            __threadfence();
        }
        __syncthreads();
        if (tid == 0) atomicAdd((unsigned*)cnt, 1u);
        p ^= 1;
    }

    // ---- final loss: h(511), gt[511]
    if (tid == 0) {
        while (ld_acq(cnt) < (unsigned)STEPS * 16u) __nanosleep(20);
    }
    __syncthreads();
    if (tid < 32) {
        const float* hr = g_h[p] + (B0 + cu) * HID;
        float s = 0.0f;
        #pragma unroll
        for (int q = 0; q < 8; ++q) {
            int k = lane + 32 * q;
            s += __ldcg(hr + k) * sWd[k];
        }
        #pragma unroll
        for (int sft = 16; sft > 0; sft >>= 1)
            s += __shfl_down_sync(0xffffffffu, s, sft);
        if (lane == 0) {
            float l = s + bdec;
            float g = gt[(size_t)STEPS * BATCH + B0 + cu];
            loss_local += fmaxf(l, 0.0f) + log1pf(__expf(-fabsf(l))) - g * l;
        }
    }
    if (tid == 0) atomicAdd(out, loss_local);
}

extern "C" void kernel_launch(void* const* d_in, const int* in_sizes, int n_in,
                              void* d_out, int out_size) {
    const float* x     = (const float*)d_in[0];
    const float* gt    = (const float*)d_in[1];
    const float* W_ih  = (const float*)d_in[2];
    const float* W_hh  = (const float*)d_in[3];
    const float* b_ih  = (const float*)d_in[4];
    const float* b_hh  = (const float*)d_in[5];
    const float* W_dec = (const float*)d_in[6];
    const float* b_dec = (const float*)d_in[7];
    float* out = (float*)d_out;

    cudaFuncSetAttribute(gru_main_kernel,
                         cudaFuncAttributeMaxDynamicSharedMemorySize, SMEM_BYTES);

    gru_init_kernel<<<64, 256>>>(out);
    gru_main_kernel<<<NCTA, NTHREADS, SMEM_BYTES>>>(
        x, gt, W_ih, W_hh, b_ih, b_hh, W_dec, b_dec, out);
}

// round 9
// speedup vs baseline: 1.4336x; 1.4336x over previous
#include <cuda_runtime.h>

// ---------------------------------------------------------------------------
// GRU (511 steps) + BCE loss. Persistent, 256 CTAs (16 batch x 16 unit
// groups), 2 CTAs/SM. CTA: 16 rows x 16 units (48 gate rows), K=384 stored
// as 8 interleaved slices of [32 h | 16 x | 4 pad] floats (SLICE_F=52).
// Thread: 4 rows x 2 units x 3 gates x 1 K-slice; fma.rn.f32x2; K-reduction
// via 3-level shfl-xor reduce-scatter. lane = rq*8+ks, warp = unit-pair.
// R9: release/acquire sync (no per-thread membar), REDG arrive, x(t+1)
// pre-staged during step t (one fewer barrier per step).
// ---------------------------------------------------------------------------

#define BATCH 256
#define IN_DIM 128
#define HID 256
#define STEPS 511
#define NCTA 256
#define NTHREADS 256
#define SLICE_F 52
#define ROW_F (8 * SLICE_F)              // 416 floats per logical row

#define OFF_W 0                          // 48 gate-rows
#define OFF_A (48 * ROW_F)               // 19968
#define OFF_SB (OFF_A + 16 * ROW_F)      // 26624
#define OFF_WD (OFF_SB + 64)             // 26688
#define SMEM_FLOATS (OFF_WD + 256)       // 26944
#define SMEM_BYTES (SMEM_FLOATS * 4)     // 107776

typedef unsigned long long u64;

__device__ float    g_h[2][BATCH * HID];
__device__ unsigned g_arr[16 * 32];

__global__ void gru_init_kernel(float* out) {
    int i = blockIdx.x * blockDim.x + threadIdx.x;
    if (i == 0) out[0] = 0.0f;
    if (i < 16 * 32) g_arr[i] = 0u;
    for (int j = i; j < BATCH * HID; j += gridDim.x * blockDim.x)
        g_h[0][j] = 0.0f;
}

__device__ __forceinline__ u64 ffma2(u64 a, u64 b, u64 c) {
    u64 d;
    asm("fma.rn.f32x2 %0, %1, %2, %3;" : "=l"(d) : "l"(a), "l"(b), "l"(c));
    return d;
}
__device__ __forceinline__ u64 addf2(u64 a, u64 b) {
    u64 d;
    asm("add.rn.f32x2 %0, %1, %2;" : "=l"(d) : "l"(a), "l"(b));
    return d;
}
__device__ __forceinline__ float sum2(u64 u) {
    return __uint_as_float((unsigned)u) + __uint_as_float((unsigned)(u >> 32));
}
__device__ __forceinline__ float sigf(float v) { return 1.0f / (1.0f + __expf(-v)); }
__device__ __forceinline__ unsigned ld_acq(const unsigned* p) {
    unsigned v;
    asm volatile("ld.acquire.gpu.global.u32 %0, [%1];" : "=r"(v) : "l"(p) : "memory");
    return v;
}
__device__ __forceinline__ void red_release(unsigned* p) {
    asm volatile("red.release.gpu.global.add.u32 [%0], %1;" :: "l"(p), "r"(1u) : "memory");
}

__global__ __launch_bounds__(NTHREADS, 2)
void gru_main_kernel(const float* __restrict__ x, const float* __restrict__ gt,
                     const float* __restrict__ W_ih, const float* __restrict__ W_hh,
                     const float* __restrict__ b_ih, const float* __restrict__ b_hh,
                     const float* __restrict__ W_dec, const float* __restrict__ b_dec,
                     float* __restrict__ out)
{
    extern __shared__ float smem[];
    float* sW  = smem + OFF_W;
    float* sA  = smem + OFF_A;
    float* sb  = smem + OFF_SB;
    float* sWd = smem + OFF_WD;

    const int tid = threadIdx.x;
    const int cb  = blockIdx.x & 15;
    const int cu  = blockIdx.x >> 4;
    const int B0  = cb * 16;
    const int U0  = cu * 16;

    const int lane = tid & 31;
    const int up   = tid >> 5;            // warp: units 2up, 2up+1
    const int ks   = lane & 7;            // K-slice
    const int rq   = lane >> 3;           // row-quad (rows 4rq..4rq+3)

    // ---- persistent W (48 gate-rows x 384 k, interleaved slices) + biases
    for (int idx = tid; idx < 48 * 384; idx += NTHREADS) {
        int gr = idx / 384, k = idx - gr * 384;
        int g = gr >> 4, uu = gr & 15, wrow = g * HID + U0 + uu;
        int s, o; float v;
        if (k < HID) { s = k >> 5; o = k & 31; v = W_hh[wrow * HID + k]; }
        else { int kx = k - HID; s = kx >> 4; o = 32 + (kx & 15); v = W_ih[wrow * IN_DIM + kx]; }
        sW[gr * ROW_F + s * SLICE_F + o] = v;
    }
    if (tid < 16) {
        sb[tid]      = b_ih[U0 + tid] + b_hh[U0 + tid];
        sb[16 + tid] = b_ih[HID + U0 + tid] + b_hh[HID + U0 + tid];
        sb[32 + tid] = b_ih[2 * HID + U0 + tid];
        sb[48 + tid] = b_hh[2 * HID + U0 + tid];
    }
    sWd[tid] = W_dec[tid];

    const float bdec = b_dec[0];
    float loss_local = 0.0f;
    int p = 0;

    const ulonglong2* Ab = (const ulonglong2*)sA + rq * 4 * 104 + ks * 13;
    const ulonglong2* Wb = (const ulonglong2*)sW + up * 2 * 104 + ks * 13;
    unsigned* cnt = &g_arr[cb * 32];

    // x-staging geometry (fixed per thread)
    const int xrow = tid >> 4;
    float* xdst0 = sA + xrow * ROW_F + 32;           // + (idx>>2)*SLICE_F + 4*(idx&3)

    // ---- prologue: stage x(0)
    {
        const float4* src = (const float4*)(x + (size_t)(B0 + xrow) * IN_DIM);
        #pragma unroll
        for (int q = 0; q < 2; ++q) {
            int idx = (tid & 15) + 16 * q;
            float4 v = __ldg(src + idx);
            *(float4*)(xdst0 + (idx >> 2) * SLICE_F + 4 * (idx & 3)) = v;
        }
    }
    __syncthreads();

    for (int t = 0; t < STEPS; ++t) {
        u64 acc[4][2][4];                  // [r,z,nh,ni][u2][row j]
        #pragma unroll
        for (int g = 0; g < 4; ++g)
            #pragma unroll
            for (int u2 = 0; u2 < 2; ++u2)
                #pragma unroll
                for (int j = 0; j < 4; ++j) acc[g][u2][j] = 0ull;

        #define GSTEP(I, NQ) {                                             \
            ulonglong2 a0 = Ab[I], a1 = Ab[104 + (I)],                     \
                       a2 = Ab[208 + (I)], a3 = Ab[312 + (I)];             \
            _Pragma("unroll")                                              \
            for (int u2 = 0; u2 < 2; ++u2) {                               \
                ulonglong2 wr = Wb[u2 * 104 + (I)];                        \
                ulonglong2 wz = Wb[(16 + u2) * 104 + (I)];                 \
                ulonglong2 wn = Wb[(32 + u2) * 104 + (I)];                 \
                acc[0][u2][0] = ffma2(a0.x, wr.x, acc[0][u2][0]);          \
                acc[0][u2][0] = ffma2(a0.y, wr.y, acc[0][u2][0]);          \
                acc[0][u2][1] = ffma2(a1.x, wr.x, acc[0][u2][1]);          \
                acc[0][u2][1] = ffma2(a1.y, wr.y, acc[0][u2][1]);          \
                acc[0][u2][2] = ffma2(a2.x, wr.x, acc[0][u2][2]);          \
                acc[0][u2][2] = ffma2(a2.y, wr.y, acc[0][u2][2]);          \
                acc[0][u2][3] = ffma2(a3.x, wr.x, acc[0][u2][3]);          \
                acc[0][u2][3] = ffma2(a3.y, wr.y, acc[0][u2][3]);          \
                acc[1][u2][0] = ffma2(a0.x, wz.x, acc[1][u2][0]);          \
                acc[1][u2][0] = ffma2(a0.y, wz.y, acc[1][u2][0]);          \
                acc[1][u2][1] = ffma2(a1.x, wz.x, acc[1][u2][1]);          \
                acc[1][u2][1] = ffma2(a1.y, wz.y, acc[1][u2][1]);          \
                acc[1][u2][2] = ffma2(a2.x, wz.x, acc[1][u2][2]);          \
                acc[1][u2][2] = ffma2(a2.y, wz.y, acc[1][u2][2]);          \
                acc[1][u2][3] = ffma2(a3.x, wz.x, acc[1][u2][3]);          \
                acc[1][u2][3] = ffma2(a3.y, wz.y, acc[1][u2][3]);          \
                acc[NQ][u2][0] = ffma2(a0.x, wn.x, acc[NQ][u2][0]);        \
                acc[NQ][u2][0] = ffma2(a0.y, wn.y, acc[NQ][u2][0]);        \
                acc[NQ][u2][1] = ffma2(a1.x, wn.x, acc[NQ][u2][1]);        \
                acc[NQ][u2][1] = ffma2(a1.y, wn.y, acc[NQ][u2][1]);        \
                acc[NQ][u2][2] = ffma2(a2.x, wn.x, acc[NQ][u2][2]);        \
                acc[NQ][u2][2] = ffma2(a2.y, wn.y, acc[NQ][u2][2]);        \
                acc[NQ][u2][3] = ffma2(a3.x, wn.x, acc[NQ][u2][3]);        \
                acc[NQ][u2][3] = ffma2(a3.y, wn.y, acc[NQ][u2][3]); } }

        // ---- x-part GEMM (quads 8..11) on pre-staged x(t), before the wait
        #pragma unroll
        for (int i = 8; i < 12; ++i) GSTEP(i, 3)

        // ---- wait for h(t)
        if (t > 0) {
            if (tid == 0) {
                unsigned target = (unsigned)t * 16u;
                while (ld_acq(cnt) < target) __nanosleep(20);
            }
            __syncthreads();
        }

        // ---- stage h(t)
        {
            int row = tid >> 4;
            const float4* src = (const float4*)(g_h[p] + (B0 + row) * HID);
            #pragma unroll
            for (int q = 0; q < 4; ++q) {
                int idx = (tid & 15) + 16 * q;
                float4 v = __ldcg(src + idx);
                *(float4*)(sA + row * ROW_F + (idx >> 3) * SLICE_F + 4 * (idx & 7)) = v;
            }
        }
        __syncthreads();

        // ---- loss for h(t) (row B0+cu), warp 0
        if (tid < 32 && t > 0) {
            float s = 0.0f;
            #pragma unroll
            for (int q = 0; q < 8; ++q)
                s += sA[cu * ROW_F + q * SLICE_F + lane] * sWd[q * 32 + lane];
            #pragma unroll
            for (int sft = 16; sft > 0; sft >>= 1)
                s += __shfl_down_sync(0xffffffffu, s, sft);
            if (lane == 0) {
                float l = s + bdec;
                float g = gt[t * BATCH + B0 + cu];
                loss_local += fmaxf(l, 0.0f) + log1pf(__expf(-fabsf(l))) - g * l;
            }
        }

        // ---- h-part GEMM (quads 0..7)
        #pragma unroll
        for (int i = 0; i < 8; ++i) GSTEP(i, 2)
        #undef GSTEP

        // ---- reduce-scatter over the 8 ks lanes (owner: row ks&3, unit ks>>2)
        const int selu = ks >> 2, selj1 = (ks >> 1) & 1, selj0 = ks & 1;
        u64 w1[4][4], w2[4][2], w3[4];
        #pragma unroll
        for (int g = 0; g < 4; ++g)
            #pragma unroll
            for (int j = 0; j < 4; ++j) {
                u64 snd = selu ? acc[g][0][j] : acc[g][1][j];
                u64 rcv = __shfl_xor_sync(0xffffffffu, snd, 4);
                u64 kp  = selu ? acc[g][1][j] : acc[g][0][j];
                w1[g][j] = addf2(kp, rcv);
            }
        #pragma unroll
        for (int g = 0; g < 4; ++g)
            #pragma unroll
            for (int jj = 0; jj < 2; ++jj) {
                u64 snd = selj1 ? w1[g][jj] : w1[g][2 + jj];
                u64 rcv = __shfl_xor_sync(0xffffffffu, snd, 2);
                u64 kp  = selj1 ? w1[g][2 + jj] : w1[g][jj];
                w2[g][jj] = addf2(kp, rcv);
            }
        #pragma unroll
        for (int g = 0; g < 4; ++g) {
            u64 snd = selj0 ? w2[g][0] : w2[g][1];
            u64 rcv = __shfl_xor_sync(0xffffffffu, snd, 1);
            u64 kp  = selj0 ? w2[g][1] : w2[g][0];
            w3[g] = addf2(kp, rcv);
        }

        // ---- pre-stage x(t+1) into the (now dead) x-region
        if (t + 1 < STEPS) {
            const float4* src = (const float4*)(x + ((size_t)(t + 1) * BATCH + B0 + xrow) * IN_DIM);
            #pragma unroll
            for (int q = 0; q < 2; ++q) {
                int idx = (tid & 15) + 16 * q;
                float4 v = __ldg(src + idx);
                *(float4*)(xdst0 + (idx >> 2) * SLICE_F + 4 * (idx & 3)) = v;
            }
        }

        // ---- epilogue: one h element per thread (no per-thread membar)
        {
            int orow  = rq * 4 + (ks & 3);
            int ounit = 2 * up + (ks >> 2);
            float rv = sigf(sum2(w3[0]) + sb[ounit]);
            float zv = sigf(sum2(w3[1]) + sb[16 + ounit]);
            float nh = sum2(w3[2]) + sb[48 + ounit];
            float ni = sum2(w3[3]) + sb[32 + ounit];
            float pre = ni + rv * nh;
            float nv = 2.0f * sigf(2.0f * pre) - 1.0f;    // tanh
            int kcol = U0 + ounit;
            float hp = sA[orow * ROW_F + (kcol >> 5) * SLICE_F + (kcol & 31)];
            float hn = nv + zv * (hp - nv);
            g_h[p ^ 1][(B0 + orow) * HID + kcol] = hn;
        }
        __syncthreads();
        if (tid == 0) red_release(cnt);    // publishes all CTA stores (bar + release)
        p ^= 1;
    }

    // ---- final loss: h(511), gt[511]
    if (tid == 0) {
        while (ld_acq(cnt) < (unsigned)STEPS * 16u) __nanosleep(20);
    }
    __syncthreads();
    if (tid < 32) {
        const float* hr = g_h[p] + (B0 + cu) * HID;
        float s = 0.0f;
        #pragma unroll
        for (int q = 0; q < 8; ++q) {
            int k = lane + 32 * q;
            s += __ldcg(hr + k) * sWd[k];
        }
        #pragma unroll
        for (int sft = 16; sft > 0; sft >>= 1)
            s += __shfl_down_sync(0xffffffffu, s, sft);
        if (lane == 0) {
            float l = s + bdec;
            float g = gt[(size_t)STEPS * BATCH + B0 + cu];
            loss_local += fmaxf(l, 0.0f) + log1pf(__expf(-fabsf(l))) - g * l;
        }
    }
    if (tid == 0) atomicAdd(out, loss_local);
}

extern "C" void kernel_launch(void* const* d_in, const int* in_sizes, int n_in,
                              void* d_out, int out_size) {
    const float* x     = (const float*)d_in[0];
    const float* gt    = (const float*)d_in[1];
    const float* W_ih  = (const float*)d_in[2];
    const float* W_hh  = (const float*)d_in[3];
    const float* b_ih  = (const float*)d_in[4];
    const float* b_hh  = (const float*)d_in[5];
    const float* W_dec = (const float*)d_in[6];
    const float* b_dec = (const float*)d_in[7];
    float* out = (float*)d_out;

    cudaFuncSetAttribute(gru_main_kernel,
                         cudaFuncAttributeMaxDynamicSharedMemorySize, SMEM_BYTES);

    gru_init_kernel<<<64, 256>>>(out);
    gru_main_kernel<<<NCTA, NTHREADS, SMEM_BYTES>>>(
        x, gt, W_ih, W_hh, b_ih, b_hh, W_dec, b_dec, out);
}

// round 10
// speedup vs baseline: 1.9523x; 1.3618x over previous
#include <cuda_runtime.h>

// ---------------------------------------------------------------------------
// GRU (511 steps) + BCE loss via tensor cores (mma.sync m16n8k8 tf32).
// Persistent, 256 CTAs (16 batch-groups x 16 unit-groups), 2 CTAs/SM.
// CTA GEMM per step: [16 rows] x [64 cols: r16|z16|nh16|ni16] x K=384.
//   - W smem: 48 physical gate rows x 384 k (tf32-rounded). Output cols
//     32-47 (nh) read rows 32-47 at k<256; cols 48-63 (ni) read rows 32-47
//     at k>=256 (k-tile masking, no zero fill).
//   - 8 warps = 2 N-halves x 4 K-quarters; smem tree K-reduction.
// State h and loss decode stay fp32; only mma inputs are tf32-rounded.
// ---------------------------------------------------------------------------

#define BATCH 256
#define IN_DIM 128
#define HID 256
#define STEPS 511
#define NCTA 256
#define NTHREADS 256
#define ASTR 388
#define WSTR 388

// smem float offsets
#define OFF_W   0                         // 48 x WSTR = 18624
#define OFF_A   18624                     // 16 x ASTR = 6208
#define OFF_SCR 24832                     // 4 regions x 16 x 36 = 2304
#define OFF_G   27136                     // gatebuf 16 x 68 = 1088
#define OFF_SB  28224                     // biases 64
#define OFF_WD  28288                     // W_dec 256
#define SMEM_FLOATS 28544
#define SMEM_BYTES (SMEM_FLOATS * 4)      // 114176

typedef unsigned int u32;

__device__ float g_h[2][BATCH * HID];
__device__ unsigned g_arr[16 * 32];

__global__ void gru_init_kernel(float* out) {
    int i = blockIdx.x * blockDim.x + threadIdx.x;
    if (i == 0) out[0] = 0.0f;
    if (i < 16 * 32) g_arr[i] = 0u;
    for (int j = i; j < BATCH * HID; j += gridDim.x * blockDim.x)
        g_h[0][j] = 0.0f;
}

__device__ __forceinline__ float tf32r(float f) {
    u32 u;
    asm("cvt.rna.tf32.f32 %0, %1;" : "=r"(u) : "f"(f));
    return __uint_as_float(u);
}
__device__ __forceinline__ void mma8(float* c, u32 a0, u32 a1, u32 a2, u32 a3,
                                     u32 b0, u32 b1) {
    asm volatile(
        "mma.sync.aligned.m16n8k8.row.col.f32.tf32.tf32.f32 "
        "{%0,%1,%2,%3}, {%4,%5,%6,%7}, {%8,%9}, {%0,%1,%2,%3};"
        : "+f"(c[0]), "+f"(c[1]), "+f"(c[2]), "+f"(c[3])
        : "r"(a0), "r"(a1), "r"(a2), "r"(a3), "r"(b0), "r"(b1));
}
__device__ __forceinline__ float sigf(float v) { return 1.0f / (1.0f + __expf(-v)); }
__device__ __forceinline__ unsigned ld_acq(const unsigned* p) {
    unsigned v;
    asm volatile("ld.acquire.gpu.global.u32 %0, [%1];" : "=r"(v) : "l"(p) : "memory");
    return v;
}
__device__ __forceinline__ void red_release(unsigned* p) {
    asm volatile("red.release.gpu.global.add.u32 [%0], %1;" :: "l"(p), "r"(1u) : "memory");
}

__global__ __launch_bounds__(NTHREADS, 2)
void gru_main_kernel(const float* __restrict__ x, const float* __restrict__ gt,
                     const float* __restrict__ W_ih, const float* __restrict__ W_hh,
                     const float* __restrict__ b_ih, const float* __restrict__ b_hh,
                     const float* __restrict__ W_dec, const float* __restrict__ b_dec,
                     float* __restrict__ out)
{
    extern __shared__ float smem[];
    float* sW  = smem + OFF_W;
    float* sA  = smem + OFF_A;
    float* scr = smem + OFF_SCR;
    float* gb  = smem + OFF_G;
    float* sb  = smem + OFF_SB;
    float* sWd = smem + OFF_WD;

    const int tid  = threadIdx.x;
    const int cb   = blockIdx.x & 15;
    const int cu   = blockIdx.x >> 4;
    const int B0   = cb * 16;
    const int U0   = cu * 16;

    const int lane = tid & 31;
    const int wid  = tid >> 5;
    const int nh   = wid & 1;             // N-half (cols 32*nh .. +31)
    const int kq   = wid >> 1;            // K-quarter (ktiles 12kq..12kq+11)
    const int lg   = lane >> 2;           // group id 0..7
    const int lt   = lane & 3;            // thread-in-group

    // ---- persistent W (tf32-rounded), biases, W_dec
    for (int idx = tid; idx < 48 * 384; idx += NTHREADS) {
        int gr = idx / 384, k = idx - gr * 384;
        int g = gr >> 4, uu = gr & 15, grow = g * HID + U0 + uu;
        float v = (k < HID) ? W_hh[grow * HID + k] : W_ih[grow * IN_DIM + (k - HID)];
        sW[gr * WSTR + k] = tf32r(v);
    }
    if (tid < 16) {
        sb[tid]      = b_ih[U0 + tid] + b_hh[U0 + tid];              // r
        sb[16 + tid] = b_ih[HID + U0 + tid] + b_hh[HID + U0 + tid];  // z
        sb[32 + tid] = b_hh[2 * HID + U0 + tid];                     // n (h side)
        sb[48 + tid] = b_ih[2 * HID + U0 + tid];                     // n (x side)
    }
    sWd[tid] = W_dec[tid];
    __syncthreads();

    const float bdec = b_dec[0];
    float loss_local = 0.0f;
    int p = 0;
    unsigned* cnt = &g_arr[cb * 32];

    // fragment base pointers
    const float* aP = sA + lg * ASTR + lt;              // + kb (+4) (+8*ASTR)
    const float* bP[4];
    #pragma unroll
    for (int nt4 = 0; nt4 < 4; ++nt4) {
        int nt = 4 * nh + nt4;
        int ncol = 8 * nt + lg;
        int prow = (nt >= 6) ? (ncol - 16) : ncol;      // ni maps to rows 32-47
        bP[nt4] = sW + prow * WSTR + lt;
    }

    // ---- stage x(0) (tf32-rounded) into sA x-region
    {
        int row = tid >> 4;
        const float4* src = (const float4*)(x + (size_t)(B0 + row) * IN_DIM);
        #pragma unroll
        for (int q = 0; q < 2; ++q) {
            int k4 = (tid & 15) + 16 * q;
            float4 v = __ldg(src + k4);
            v.x = tf32r(v.x); v.y = tf32r(v.y); v.z = tf32r(v.z); v.w = tf32r(v.w);
            *(float4*)(sA + row * ASTR + HID + 4 * k4) = v;
        }
    }
    __syncthreads();

    for (int t = 0; t < STEPS; ++t) {
        // ---- wait for h(t)
        if (t > 0) {
            if (tid == 0) {
                unsigned target = (unsigned)t * 16u;
                while (ld_acq(cnt) < target) __nanosleep(20);
            }
            __syncthreads();
        }

        // ---- stage h(t) (tf32-rounded)
        {
            int row = tid >> 4;
            const float4* src = (const float4*)(g_h[p] + (B0 + row) * HID);
            #pragma unroll
            for (int q = 0; q < 4; ++q) {
                int k4 = (tid & 15) + 16 * q;
                float4 v = __ldcg(src + k4);
                v.x = tf32r(v.x); v.y = tf32r(v.y); v.z = tf32r(v.z); v.w = tf32r(v.w);
                *(float4*)(sA + row * ASTR + 4 * k4) = v;
            }
        }
        __syncthreads();

        // ---- MMA phase: 12 k-tiles, 4 n-tiles (masked)
        float c[4][4];
        #pragma unroll
        for (int i = 0; i < 4; ++i)
            #pragma unroll
            for (int j = 0; j < 4; ++j) c[i][j] = 0.0f;

        #pragma unroll 4
        for (int ki = 0; ki < 12; ++ki) {
            int kt = 12 * kq + ki;
            int kb = 8 * kt;
            u32 a0 = __float_as_uint(aP[kb]);
            u32 a1 = __float_as_uint(aP[kb + 8 * ASTR]);
            u32 a2 = __float_as_uint(aP[kb + 4]);
            u32 a3 = __float_as_uint(aP[kb + 4 + 8 * ASTR]);
            #pragma unroll
            for (int nt4 = 0; nt4 < 4; ++nt4) {
                int nt = 4 * nh + nt4;
                bool act = (nt < 4) || ((nt < 6) ? (kt < 32) : (kt >= 32));
                if (act) {
                    u32 b0 = __float_as_uint(bP[nt4][kb]);
                    u32 b1 = __float_as_uint(bP[nt4][kb + 4]);
                    mma8(c[nt4], a0, a1, a2, a3, b0, b1);
                }
            }
        }

        // ---- K reduction round 1: kq 1,3 store partials
        if (kq & 1) {
            float* R = scr + ((kq >> 1) * 2 + nh) * 576;
            #pragma unroll
            for (int nt4 = 0; nt4 < 4; ++nt4) {
                int base = lg * 36 + 8 * nt4 + 2 * lt;
                *(float2*)(R + base) = make_float2(c[nt4][0], c[nt4][1]);
                *(float2*)(R + base + 8 * 36) = make_float2(c[nt4][2], c[nt4][3]);
            }
        }
        __syncthreads();

        // ---- round 2: kq 0,2 add (kq2 stores back); pre-stage x(t+1)
        if (!(kq & 1)) {
            float* R = scr + ((kq >> 1) * 2 + nh) * 576;
            #pragma unroll
            for (int nt4 = 0; nt4 < 4; ++nt4) {
                int base = lg * 36 + 8 * nt4 + 2 * lt;
                float2 u0 = *(float2*)(R + base);
                float2 u1 = *(float2*)(R + base + 8 * 36);
                c[nt4][0] += u0.x; c[nt4][1] += u0.y;
                c[nt4][2] += u1.x; c[nt4][3] += u1.y;
            }
            if (kq == 2) {
                float* S = scr + (2 + nh) * 576;
                #pragma unroll
                for (int nt4 = 0; nt4 < 4; ++nt4) {
                    int base = lg * 36 + 8 * nt4 + 2 * lt;
                    *(float2*)(S + base) = make_float2(c[nt4][0], c[nt4][1]);
                    *(float2*)(S + base + 8 * 36) = make_float2(c[nt4][2], c[nt4][3]);
                }
            }
        }
        if (t + 1 < STEPS) {
            int row = tid >> 4;
            const float4* src = (const float4*)(x + ((size_t)(t + 1) * BATCH + B0 + row) * IN_DIM);
            #pragma unroll
            for (int q = 0; q < 2; ++q) {
                int k4 = (tid & 15) + 16 * q;
                float4 v = __ldg(src + k4);
                v.x = tf32r(v.x); v.y = tf32r(v.y); v.z = tf32r(v.z); v.w = tf32r(v.w);
                *(float4*)(sA + row * ASTR + HID + 4 * k4) = v;
            }
        }
        __syncthreads();

        // ---- round 3: kq0 adds kq2's sum, writes gatebuf
        if (kq == 0) {
            float* S = scr + (2 + nh) * 576;
            #pragma unroll
            for (int nt4 = 0; nt4 < 4; ++nt4) {
                int base = lg * 36 + 8 * nt4 + 2 * lt;
                float2 u0 = *(float2*)(S + base);
                float2 u1 = *(float2*)(S + base + 8 * 36);
                c[nt4][0] += u0.x; c[nt4][1] += u0.y;
                c[nt4][2] += u1.x; c[nt4][3] += u1.y;
                int gcol = 32 * nh + 8 * nt4 + 2 * lt;
                *(float2*)(gb + lg * 68 + gcol) = make_float2(c[nt4][0], c[nt4][1]);
                *(float2*)(gb + (lg + 8) * 68 + gcol) = make_float2(c[nt4][2], c[nt4][3]);
            }
        }
        __syncthreads();

        // ---- epilogue: one h element per thread (fp32 state path)
        {
            int row = tid >> 4, u = tid & 15;
            float rr = gb[row * 68 + u];
            float zz = gb[row * 68 + 16 + u];
            float hh = gb[row * 68 + 32 + u];
            float ii = gb[row * 68 + 48 + u];
            float hp = __ldcg(&g_h[p][(B0 + row) * HID + U0 + u]);   // fp32 h(t)
            float rv = sigf(rr + sb[u]);
            float zv = sigf(zz + sb[16 + u]);
            float pre = ii + sb[48 + u] + rv * (hh + sb[32 + u]);
            float nv = 2.0f * sigf(2.0f * pre) - 1.0f;               // tanh
            float hn = nv + zv * (hp - nv);
            g_h[p ^ 1][(B0 + row) * HID + U0 + u] = hn;
        }

        // ---- loss for h(t) (fp32 decode from g_h), warp 0
        if (tid < 32 && t > 0) {
            const float* hr = g_h[p] + (B0 + cu) * HID;
            float s = 0.0f;
            #pragma unroll
            for (int q = 0; q < 8; ++q) {
                int k = lane + 32 * q;
                s += __ldcg(hr + k) * sWd[k];
            }
            #pragma unroll
            for (int sft = 16; sft > 0; sft >>= 1)
                s += __shfl_down_sync(0xffffffffu, s, sft);
            if (lane == 0) {
                float l = s + bdec;
                float g = gt[t * BATCH + B0 + cu];
                loss_local += fmaxf(l, 0.0f) + log1pf(__expf(-fabsf(l))) - g * l;
            }
        }
        __syncthreads();
        if (tid == 0) red_release(cnt);
        p ^= 1;
    }

    // ---- final loss: h(511), gt[511]
    if (tid == 0) {
        while (ld_acq(cnt) < (unsigned)STEPS * 16u) __nanosleep(20);
    }
    __syncthreads();
    if (tid < 32) {
        const float* hr = g_h[p] + (B0 + cu) * HID;
        float s = 0.0f;
        #pragma unroll
        for (int q = 0; q < 8; ++q) {
            int k = lane + 32 * q;
            s += __ldcg(hr + k) * sWd[k];
        }
        #pragma unroll
        for (int sft = 16; sft > 0; sft >>= 1)
            s += __shfl_down_sync(0xffffffffu, s, sft);
        if (lane == 0) {
            float l = s + bdec;
            float g = gt[(size_t)STEPS * BATCH + B0 + cu];
            loss_local += fmaxf(l, 0.0f) + log1pf(__expf(-fabsf(l))) - g * l;
        }
    }
    if (tid == 0) atomicAdd(out, loss_local);
}

extern "C" void kernel_launch(void* const* d_in, const int* in_sizes, int n_in,
                              void* d_out, int out_size) {
    const float* x     = (const float*)d_in[0];
    const float* gt    = (const float*)d_in[1];
    const float* W_ih  = (const float*)d_in[2];
    const float* W_hh  = (const float*)d_in[3];
    const float* b_ih  = (const float*)d_in[4];
    const float* b_hh  = (const float*)d_in[5];
    const float* W_dec = (const float*)d_in[6];
    const float* b_dec = (const float*)d_in[7];
    float* out = (float*)d_out;

    cudaFuncSetAttribute(gru_main_kernel,
                         cudaFuncAttributeMaxDynamicSharedMemorySize, SMEM_BYTES);

    gru_init_kernel<<<64, 256>>>(out);
    gru_main_kernel<<<NCTA, NTHREADS, SMEM_BYTES>>>(
        x, gt, W_ih, W_hh, b_ih, b_hh, W_dec, b_dec, out);
}

// round 11
// speedup vs baseline: 2.4401x; 1.2499x over previous
#include <cuda_runtime.h>

// ---------------------------------------------------------------------------
// GRU (511 steps) + BCE via mma.sync m16n8k8 tf32. Persistent, 256 CTAs
// (16 batch x 16 unit groups), 2 CTAs/SM.
// CTA GEMM/step: [16 rows] x [64 cols: r16|z16|nh16|ni16] x K=384.
// Warps: nq = wid&3 (16-col n-quarter), kq = wid>>2 (K parity, kt=2i+kq).
//   nq0/1: r/z (all kt); nq2: nh (h-ktiles only); nq3: ni (x-ktiles only).
// x-part MMA (kt>=32) runs BEFORE the inter-CTA wait. One-round K-reduce.
// State h + loss decode stay fp32; mma inputs tf32-rounded.
// ---------------------------------------------------------------------------

#define BATCH 256
#define IN_DIM 128
#define HID 256
#define STEPS 511
#define NCTA 256
#define NTHREADS 256
#define ASTR 388
#define WSTR 388

#define OFF_W   0                         // 48 x 388 = 18624
#define OFF_A   18624                     // 16 x 388 = 6208
#define OFF_SCR 24832                     // 4 x 288 = 1152
#define OFF_G   25984                     // 16 x 68 = 1088
#define OFF_SB  27072                     // 64
#define OFF_WD  27136                     // 256
#define SMEM_FLOATS 27392
#define SMEM_BYTES (SMEM_FLOATS * 4)      // 109568 (x2 = 219KB/SM)

typedef unsigned int u32;

__device__ float g_h[2][BATCH * HID];
__device__ unsigned g_arr[16 * 32];

__global__ void gru_init_kernel(float* out) {
    int i = blockIdx.x * blockDim.x + threadIdx.x;
    if (i == 0) out[0] = 0.0f;
    if (i < 16 * 32) g_arr[i] = 0u;
    for (int j = i; j < BATCH * HID; j += gridDim.x * blockDim.x)
        g_h[0][j] = 0.0f;
}

__device__ __forceinline__ float tf32r(float f) {
    u32 u;
    asm("cvt.rna.tf32.f32 %0, %1;" : "=r"(u) : "f"(f));
    return __uint_as_float(u);
}
__device__ __forceinline__ void mma8(float* c, u32 a0, u32 a1, u32 a2, u32 a3,
                                     u32 b0, u32 b1) {
    asm volatile(
        "mma.sync.aligned.m16n8k8.row.col.f32.tf32.tf32.f32 "
        "{%0,%1,%2,%3}, {%4,%5,%6,%7}, {%8,%9}, {%0,%1,%2,%3};"
        : "+f"(c[0]), "+f"(c[1]), "+f"(c[2]), "+f"(c[3])
        : "r"(a0), "r"(a1), "r"(a2), "r"(a3), "r"(b0), "r"(b1));
}
__device__ __forceinline__ float sigf(float v) { return 1.0f / (1.0f + __expf(-v)); }
__device__ __forceinline__ unsigned ld_acq(const unsigned* p) {
    unsigned v;
    asm volatile("ld.acquire.gpu.global.u32 %0, [%1];" : "=r"(v) : "l"(p) : "memory");
    return v;
}
__device__ __forceinline__ void red_release(unsigned* p) {
    asm volatile("red.release.gpu.global.add.u32 [%0], %1;" :: "l"(p), "r"(1u) : "memory");
}

__global__ __launch_bounds__(NTHREADS, 2)
void gru_main_kernel(const float* __restrict__ x, const float* __restrict__ gt,
                     const float* __restrict__ W_ih, const float* __restrict__ W_hh,
                     const float* __restrict__ b_ih, const float* __restrict__ b_hh,
                     const float* __restrict__ W_dec, const float* __restrict__ b_dec,
                     float* __restrict__ out)
{
    extern __shared__ float smem[];
    float* sW  = smem + OFF_W;
    float* sA  = smem + OFF_A;
    float* scr = smem + OFF_SCR;
    float* gb  = smem + OFF_G;
    float* sb  = smem + OFF_SB;
    float* sWd = smem + OFF_WD;

    const int tid  = threadIdx.x;
    const int cb   = blockIdx.x & 15;
    const int cu   = blockIdx.x >> 4;
    const int B0   = cb * 16;
    const int U0   = cu * 16;

    const int lane = tid & 31;
    const int wid  = tid >> 5;
    const int nq   = wid & 3;             // n-quarter: cols 16nq..16nq+15
    const int kq   = wid >> 2;            // K parity: kt = 2i + kq
    const int lg   = lane >> 2;
    const int lt   = lane & 3;

    // ---- persistent W (tf32-rounded), biases, W_dec
    for (int idx = tid; idx < 48 * 384; idx += NTHREADS) {
        int gr = idx / 384, k = idx - gr * 384;
        int g = gr >> 4, uu = gr & 15, grow = g * HID + U0 + uu;
        float v = (k < HID) ? W_hh[grow * HID + k] : W_ih[grow * IN_DIM + (k - HID)];
        sW[gr * WSTR + k] = tf32r(v);
    }
    if (tid < 16) {
        sb[tid]      = b_ih[U0 + tid] + b_hh[U0 + tid];              // r
        sb[16 + tid] = b_ih[HID + U0 + tid] + b_hh[HID + U0 + tid];  // z
        sb[32 + tid] = b_hh[2 * HID + U0 + tid];                     // n (h side)
        sb[48 + tid] = b_ih[2 * HID + U0 + tid];                     // n (x side)
    }
    sWd[tid] = W_dec[tid];

    const float bdec = b_dec[0];
    float loss_local = 0.0f;
    int p = 0;
    unsigned* cnt = &g_arr[cb * 32];

    // fragment pointers (A offset folds in kq: kb = 8*(2i+kq) = 16i + 8kq)
    const float* aP = sA + lg * ASTR + lt + 8 * kq;
    const float* bP[2];
    #pragma unroll
    for (int ntl = 0; ntl < 2; ++ntl) {
        int nt = 2 * nq + ntl;
        int ncol = 8 * nt + lg;
        int prow = (ncol < 48) ? ncol : ncol - 16;    // ni cols 48-63 -> rows 32-47
        bP[ntl] = sW + prow * WSTR + lt + 8 * kq;
    }
    const int erow = tid >> 4, eu = tid & 15;          // epilogue element
    float* scrW = scr + nq * 288 + lg * 18 + 2 * lt;   // (+ ntl*8, + 8*18 rows)
    float* gbW  = gb + lg * 68 + nq * 16 + 2 * lt;

    // ---- stage x(0) (tf32-rounded)
    {
        int row = tid >> 4;
        const float4* src = (const float4*)(x + (size_t)(B0 + row) * IN_DIM);
        #pragma unroll
        for (int q = 0; q < 2; ++q) {
            int k4 = (tid & 15) + 16 * q;
            float4 v = __ldg(src + k4);
            v.x = tf32r(v.x); v.y = tf32r(v.y); v.z = tf32r(v.z); v.w = tf32r(v.w);
            *(float4*)(sA + row * ASTR + HID + 4 * k4) = v;
        }
    }
    __syncthreads();

    for (int t = 0; t < STEPS; ++t) {
        float c[2][4] = {{0.f,0.f,0.f,0.f},{0.f,0.f,0.f,0.f}};

        // ---- x-part MMA (kt = 32..47, this warp's parity) BEFORE the wait
        if (nq != 2) {
            #pragma unroll
            for (int i = 16; i < 24; ++i) {
                const float* a = aP + 16 * i;
                u32 a0 = __float_as_uint(a[0]);
                u32 a1 = __float_as_uint(a[8 * ASTR]);
                u32 a2 = __float_as_uint(a[4]);
                u32 a3 = __float_as_uint(a[4 + 8 * ASTR]);
                #pragma unroll
                for (int ntl = 0; ntl < 2; ++ntl) {
                    const float* b = bP[ntl] + 16 * i;
                    mma8(c[ntl], a0, a1, a2, a3,
                         __float_as_uint(b[0]), __float_as_uint(b[4]));
                }
            }
        }

        // ---- wait for h(t)
        if (t > 0) {
            if (tid == 0) {
                unsigned target = (unsigned)t * 16u;
                while (ld_acq(cnt) < target) __nanosleep(20);
            }
            __syncthreads();
        }

        // ---- stage h(t) (tf32-rounded)
        {
            int row = tid >> 4;
            const float4* src = (const float4*)(g_h[p] + (B0 + row) * HID);
            #pragma unroll
            for (int q = 0; q < 4; ++q) {
                int k4 = (tid & 15) + 16 * q;
                float4 v = __ldcg(src + k4);
                v.x = tf32r(v.x); v.y = tf32r(v.y); v.z = tf32r(v.z); v.w = tf32r(v.w);
                *(float4*)(sA + row * ASTR + 4 * k4) = v;
            }
        }
        __syncthreads();

        // ---- prefetch fp32 h(t) element for the epilogue (hides under MMA)
        float hp = __ldcg(&g_h[p][(B0 + erow) * HID + U0 + eu]);

        // ---- loss for h(t) on the h-idle warp (nq3,kq0 = wid 3)
        if (wid == 3 && t > 0) {
            const float* hr = g_h[p] + (B0 + cu) * HID;
            float s = 0.0f;
            #pragma unroll
            for (int q = 0; q < 8; ++q) {
                int k = lane + 32 * q;
                s += __ldcg(hr + k) * sWd[k];
            }
            #pragma unroll
            for (int sft = 16; sft > 0; sft >>= 1)
                s += __shfl_down_sync(0xffffffffu, s, sft);
            if (lane == 0) {
                float l = s + bdec;
                float g = gt[t * BATCH + B0 + cu];
                loss_local += fmaxf(l, 0.0f) + log1pf(__expf(-fabsf(l))) - g * l;
            }
        }

        // ---- h-part MMA (kt = 0..31, this warp's parity)
        if (nq != 3) {
            #pragma unroll
            for (int i = 0; i < 16; ++i) {
                const float* a = aP + 16 * i;
                u32 a0 = __float_as_uint(a[0]);
                u32 a1 = __float_as_uint(a[8 * ASTR]);
                u32 a2 = __float_as_uint(a[4]);
                u32 a3 = __float_as_uint(a[4 + 8 * ASTR]);
                #pragma unroll
                for (int ntl = 0; ntl < 2; ++ntl) {
                    const float* b = bP[ntl] + 16 * i;
                    mma8(c[ntl], a0, a1, a2, a3,
                         __float_as_uint(b[0]), __float_as_uint(b[4]));
                }
            }
        }

        // ---- kq1 stores partials; everyone restages x(t+1)
        if (kq == 1) {
            #pragma unroll
            for (int ntl = 0; ntl < 2; ++ntl) {
                *(float2*)(scrW + ntl * 8)          = make_float2(c[ntl][0], c[ntl][1]);
                *(float2*)(scrW + ntl * 8 + 8 * 18) = make_float2(c[ntl][2], c[ntl][3]);
            }
        }
        if (t + 1 < STEPS) {
            int row = tid >> 4;
            const float4* src = (const float4*)(x + ((size_t)(t + 1) * BATCH + B0 + row) * IN_DIM);
            #pragma unroll
            for (int q = 0; q < 2; ++q) {
                int k4 = (tid & 15) + 16 * q;
                float4 v = __ldg(src + k4);
                v.x = tf32r(v.x); v.y = tf32r(v.y); v.z = tf32r(v.z); v.w = tf32r(v.w);
                *(float4*)(sA + row * ASTR + HID + 4 * k4) = v;
            }
        }
        __syncthreads();

        // ---- kq0 adds partials, writes gate buffer
        if (kq == 0) {
            #pragma unroll
            for (int ntl = 0; ntl < 2; ++ntl) {
                float2 u0 = *(float2*)(scrW + ntl * 8);
                float2 u1 = *(float2*)(scrW + ntl * 8 + 8 * 18);
                *(float2*)(gbW + ntl * 8)          = make_float2(c[ntl][0] + u0.x, c[ntl][1] + u0.y);
                *(float2*)(gbW + ntl * 8 + 8 * 68) = make_float2(c[ntl][2] + u1.x, c[ntl][3] + u1.y);
            }
        }
        __syncthreads();

        // ---- epilogue: one h element per thread (fp32 state path)
        {
            float rr = gb[erow * 68 + eu];
            float zz = gb[erow * 68 + 16 + eu];
            float hh = gb[erow * 68 + 32 + eu];
            float ii = gb[erow * 68 + 48 + eu];
            float rv = sigf(rr + sb[eu]);
            float zv = sigf(zz + sb[16 + eu]);
            float pre = ii + sb[48 + eu] + rv * (hh + sb[32 + eu]);
            float nv = 2.0f * sigf(2.0f * pre) - 1.0f;               // tanh
            float hn = nv + zv * (hp - nv);
            g_h[p ^ 1][(B0 + erow) * HID + U0 + eu] = hn;
        }
        __syncthreads();
        if (tid == 0) red_release(cnt);
        p ^= 1;
    }

    // ---- final loss: h(511), gt[511]
    if (tid == 0) {
        while (ld_acq(cnt) < (unsigned)STEPS * 16u) __nanosleep(20);
    }
    __syncthreads();
    if (tid < 32) {
        const float* hr = g_h[p] + (B0 + cu) * HID;
        float s = 0.0f;
        #pragma unroll
        for (int q = 0; q < 8; ++q) {
            int k = lane + 32 * q;
            s += __ldcg(hr + k) * sWd[k];
        }
        #pragma unroll
        for (int sft = 16; sft > 0; sft >>= 1)
            s += __shfl_down_sync(0xffffffffu, s, sft);
        if (lane == 0) {
            float l = s + bdec;
            float g = gt[(size_t)STEPS * BATCH + B0 + cu];
            loss_local += fmaxf(l, 0.0f) + log1pf(__expf(-fabsf(l))) - g * l;
        }
    }
    if (tid == 0 || (wid == 3 && lane == 0)) atomicAdd(out, loss_local);
}

extern "C" void kernel_launch(void* const* d_in, const int* in_sizes, int n_in,
                              void* d_out, int out_size) {
    const float* x     = (const float*)d_in[0];
    const float* gt    = (const float*)d_in[1];
    const float* W_ih  = (const float*)d_in[2];
    const float* W_hh  = (const float*)d_in[3];
    const float* b_ih  = (const float*)d_in[4];
    const float* b_hh  = (const float*)d_in[5];
    const float* W_dec = (const float*)d_in[6];
    const float* b_dec = (const float*)d_in[7];
    float* out = (float*)d_out;

    cudaFuncSetAttribute(gru_main_kernel,
                         cudaFuncAttributeMaxDynamicSharedMemorySize, SMEM_BYTES);

    gru_init_kernel<<<64, 256>>>(out);
    gru_main_kernel<<<NCTA, NTHREADS, SMEM_BYTES>>>(
        x, gt, W_ih, W_hh, b_ih, b_hh, W_dec, b_dec, out);
}

// round 12
// speedup vs baseline: 2.4984x; 1.0239x over previous
#include <cuda_runtime.h>

// ---------------------------------------------------------------------------
// GRU (511 steps) + BCE via mma.sync m16n8k8 tf32. Persistent, 256 CTAs
// (16 batch x 16 unit groups), 2 CTAs/SM.
// CTA GEMM/step: [16 rows] x [64 cols: r16|z16|nh16|ni16] x K=384.
// Warps: nq = wid&3 (16-col n-quarter), kq = wid>>2 (K parity, kt=2i+kq).
// R12: h exchanged tf32-pre-rounded (no cvt on consumer), hp carried in a
// register (no epilogue LDG), x pre-rounded at init (g_xr), per-warp
// barrier polling (4 syncs/step). fp32 recurrence state kept via hp reg.
// ---------------------------------------------------------------------------

#define BATCH 256
#define IN_DIM 128
#define HID 256
#define STEPS 511
#define NCTA 256
#define NTHREADS 256
#define ASTR 388
#define WSTR 388

#define OFF_W   0                         // 48 x 388 = 18624
#define OFF_A   18624                     // 16 x 388 = 6208
#define OFF_SCR 24832                     // 4 x 288 = 1152
#define OFF_G   25984                     // 16 x 68 = 1088
#define OFF_SB  27072                     // 64
#define OFF_WD  27136                     // 256
#define SMEM_FLOATS 27392
#define SMEM_BYTES (SMEM_FLOATS * 4)      // 109568

typedef unsigned int u32;

__device__ float g_h[2][BATCH * HID];            // tf32-pre-rounded h
__device__ float g_xr[(size_t)STEPS * BATCH * IN_DIM];   // tf32-pre-rounded x
__device__ unsigned g_arr[16 * 32];

__device__ __forceinline__ float tf32r(float f) {
    u32 u;
    asm("cvt.rna.tf32.f32 %0, %1;" : "=r"(u) : "f"(f));
    return __uint_as_float(u);
}

__global__ void gru_init_kernel(float* out, const float* __restrict__ x) {
    int i = blockIdx.x * blockDim.x + threadIdx.x;
    int stride = gridDim.x * blockDim.x;
    if (i == 0) out[0] = 0.0f;
    if (i < 16 * 32) g_arr[i] = 0u;
    for (int j = i; j < BATCH * HID; j += stride)
        g_h[0][j] = 0.0f;
    const float4* x4 = (const float4*)x;
    float4* r4 = (float4*)g_xr;
    int n4 = (int)((size_t)STEPS * BATCH * IN_DIM / 4);
    for (int j = i; j < n4; j += stride) {
        float4 v = x4[j];
        v.x = tf32r(v.x); v.y = tf32r(v.y); v.z = tf32r(v.z); v.w = tf32r(v.w);
        r4[j] = v;
    }
}

__device__ __forceinline__ void mma8(float* c, u32 a0, u32 a1, u32 a2, u32 a3,
                                     u32 b0, u32 b1) {
    asm volatile(
        "mma.sync.aligned.m16n8k8.row.col.f32.tf32.tf32.f32 "
        "{%0,%1,%2,%3}, {%4,%5,%6,%7}, {%8,%9}, {%0,%1,%2,%3};"
        : "+f"(c[0]), "+f"(c[1]), "+f"(c[2]), "+f"(c[3])
        : "r"(a0), "r"(a1), "r"(a2), "r"(a3), "r"(b0), "r"(b1));
}
__device__ __forceinline__ float sigf(float v) { return 1.0f / (1.0f + __expf(-v)); }
__device__ __forceinline__ unsigned ld_acq(const unsigned* p) {
    unsigned v;
    asm volatile("ld.acquire.gpu.global.u32 %0, [%1];" : "=r"(v) : "l"(p) : "memory");
    return v;
}
__device__ __forceinline__ void red_release(unsigned* p) {
    asm volatile("red.release.gpu.global.add.u32 [%0], %1;" :: "l"(p), "r"(1u) : "memory");
}

__global__ __launch_bounds__(NTHREADS, 2)
void gru_main_kernel(const float* __restrict__ x, const float* __restrict__ gt,
                     const float* __restrict__ W_ih, const float* __restrict__ W_hh,
                     const float* __restrict__ b_ih, const float* __restrict__ b_hh,
                     const float* __restrict__ W_dec, const float* __restrict__ b_dec,
                     float* __restrict__ out)
{
    extern __shared__ float smem[];
    float* sW  = smem + OFF_W;
    float* sA  = smem + OFF_A;
    float* scr = smem + OFF_SCR;
    float* gb  = smem + OFF_G;
    float* sb  = smem + OFF_SB;
    float* sWd = smem + OFF_WD;

    const int tid  = threadIdx.x;
    const int cb   = blockIdx.x & 15;
    const int cu   = blockIdx.x >> 4;
    const int B0   = cb * 16;
    const int U0   = cu * 16;

    const int lane = tid & 31;
    const int wid  = tid >> 5;
    const int nq   = wid & 3;             // n-quarter: cols 16nq..16nq+15
    const int kq   = wid >> 2;            // K parity: kt = 2i + kq
    const int lg   = lane >> 2;
    const int lt   = lane & 3;

    // ---- persistent W (tf32-rounded), biases, W_dec
    for (int idx = tid; idx < 48 * 384; idx += NTHREADS) {
        int gr = idx / 384, k = idx - gr * 384;
        int g = gr >> 4, uu = gr & 15, grow = g * HID + U0 + uu;
        float v = (k < HID) ? W_hh[grow * HID + k] : W_ih[grow * IN_DIM + (k - HID)];
        sW[gr * WSTR + k] = tf32r(v);
    }
    if (tid < 16) {
        sb[tid]      = b_ih[U0 + tid] + b_hh[U0 + tid];              // r
        sb[16 + tid] = b_ih[HID + U0 + tid] + b_hh[HID + U0 + tid];  // z
        sb[32 + tid] = b_hh[2 * HID + U0 + tid];                     // n (h side)
        sb[48 + tid] = b_ih[2 * HID + U0 + tid];                     // n (x side)
    }
    sWd[tid] = W_dec[tid];

    const float bdec = b_dec[0];
    float loss_local = 0.0f;
    int p = 0;
    unsigned* cnt = &g_arr[cb * 32];

    // fragment pointers (A offset folds in kq: kb = 8*(2i+kq) = 16i + 8kq)
    const float* aP = sA + lg * ASTR + lt + 8 * kq;
    const float* bP[2];
    #pragma unroll
    for (int ntl = 0; ntl < 2; ++ntl) {
        int nt = 2 * nq + ntl;
        int ncol = 8 * nt + lg;
        int prow = (ncol < 48) ? ncol : ncol - 16;    // ni cols 48-63 -> rows 32-47
        bP[ntl] = sW + prow * WSTR + lt + 8 * kq;
    }
    const int erow = tid >> 4, eu = tid & 15;          // epilogue element
    float hp = 0.0f;                                   // fp32 h state, in-register
    float* scrW = scr + nq * 288 + lg * 18 + 2 * lt;
    float* gbW  = gb + lg * 68 + nq * 16 + 2 * lt;

    // ---- stage x(0) (pre-rounded)
    {
        int row = tid >> 4;
        const float4* src = (const float4*)(g_xr + (size_t)(B0 + row) * IN_DIM);
        #pragma unroll
        for (int q = 0; q < 2; ++q) {
            int k4 = (tid & 15) + 16 * q;
            *(float4*)(sA + row * ASTR + HID + 4 * k4) = __ldg(src + k4);
        }
    }
    __syncthreads();

    for (int t = 0; t < STEPS; ++t) {
        float c[2][4] = {{0.f,0.f,0.f,0.f},{0.f,0.f,0.f,0.f}};

        // ---- x-part MMA (kt = 32..47, this warp's parity) BEFORE the wait
        if (nq != 2) {
            #pragma unroll
            for (int i = 16; i < 24; ++i) {
                const float* a = aP + 16 * i;
                u32 a0 = __float_as_uint(a[0]);
                u32 a1 = __float_as_uint(a[8 * ASTR]);
                u32 a2 = __float_as_uint(a[4]);
                u32 a3 = __float_as_uint(a[4 + 8 * ASTR]);
                #pragma unroll
                for (int ntl = 0; ntl < 2; ++ntl) {
                    const float* b = bP[ntl] + 16 * i;
                    mma8(c[ntl], a0, a1, a2, a3,
                         __float_as_uint(b[0]), __float_as_uint(b[4]));
                }
            }
        }

        // ---- per-warp wait for h(t), then each warp stages its 2 rows
        if (t > 0) {
            if (lane == 0) {
                unsigned target = (unsigned)t * 16u;
                while (ld_acq(cnt) < target) __nanosleep(20);
            }
            __syncwarp();
        }
        {
            int row = 2 * wid + (lane >> 4);
            const float4* src = (const float4*)(g_h[p] + (B0 + row) * HID);
            #pragma unroll
            for (int q = 0; q < 4; ++q) {
                int k4 = (lane & 15) + 16 * q;
                *(float4*)(sA + row * ASTR + 4 * k4) = __ldcg(src + k4);
            }
        }
        __syncthreads();

        // ---- loss for h(t) on the h-idle warp (wid 3), from staged smem
        if (wid == 3 && t > 0) {
            const float* hr = sA + cu * ASTR;
            float s = 0.0f;
            #pragma unroll
            for (int q = 0; q < 8; ++q) {
                int k = lane + 32 * q;
                s += hr[k] * sWd[k];
            }
            #pragma unroll
            for (int sft = 16; sft > 0; sft >>= 1)
                s += __shfl_down_sync(0xffffffffu, s, sft);
            if (lane == 0) {
                float l = s + bdec;
                float g = gt[t * BATCH + B0 + cu];
                loss_local += fmaxf(l, 0.0f) + log1pf(__expf(-fabsf(l))) - g * l;
            }
        }

        // ---- h-part MMA (kt = 0..31, this warp's parity)
        if (nq != 3) {
            #pragma unroll
            for (int i = 0; i < 16; ++i) {
                const float* a = aP + 16 * i;
                u32 a0 = __float_as_uint(a[0]);
                u32 a1 = __float_as_uint(a[8 * ASTR]);
                u32 a2 = __float_as_uint(a[4]);
                u32 a3 = __float_as_uint(a[4 + 8 * ASTR]);
                #pragma unroll
                for (int ntl = 0; ntl < 2; ++ntl) {
                    const float* b = bP[ntl] + 16 * i;
                    mma8(c[ntl], a0, a1, a2, a3,
                         __float_as_uint(b[0]), __float_as_uint(b[4]));
                }
            }
        }

        // ---- kq1 stores partials; everyone restages x(t+1) (pre-rounded)
        if (kq == 1) {
            #pragma unroll
            for (int ntl = 0; ntl < 2; ++ntl) {
                *(float2*)(scrW + ntl * 8)          = make_float2(c[ntl][0], c[ntl][1]);
                *(float2*)(scrW + ntl * 8 + 8 * 18) = make_float2(c[ntl][2], c[ntl][3]);
            }
        }
        if (t + 1 < STEPS) {
            int row = tid >> 4;
            const float4* src = (const float4*)(g_xr + ((size_t)(t + 1) * BATCH + B0 + row) * IN_DIM);
            #pragma unroll
            for (int q = 0; q < 2; ++q) {
                int k4 = (tid & 15) + 16 * q;
                *(float4*)(sA + row * ASTR + HID + 4 * k4) = __ldg(src + k4);
            }
        }
        __syncthreads();

        // ---- kq0 adds partials, writes gate buffer
        if (kq == 0) {
            #pragma unroll
            for (int ntl = 0; ntl < 2; ++ntl) {
                float2 u0 = *(float2*)(scrW + ntl * 8);
                float2 u1 = *(float2*)(scrW + ntl * 8 + 8 * 18);
                *(float2*)(gbW + ntl * 8)          = make_float2(c[ntl][0] + u0.x, c[ntl][1] + u0.y);
                *(float2*)(gbW + ntl * 8 + 8 * 68) = make_float2(c[ntl][2] + u1.x, c[ntl][3] + u1.y);
            }
        }
        __syncthreads();

        // ---- epilogue: one h element per thread; fp32 state in register
        {
            float rr = gb[erow * 68 + eu];
            float zz = gb[erow * 68 + 16 + eu];
            float hh = gb[erow * 68 + 32 + eu];
            float ii = gb[erow * 68 + 48 + eu];
            float rv = sigf(rr + sb[eu]);
            float zv = sigf(zz + sb[16 + eu]);
            float pre = ii + sb[48 + eu] + rv * (hh + sb[32 + eu]);
            float nv = 2.0f * sigf(2.0f * pre) - 1.0f;               // tanh
            float hn = nv + zv * (hp - nv);
            hp = hn;                                                  // carry fp32
            g_h[p ^ 1][(B0 + erow) * HID + U0 + eu] = tf32r(hn);      // publish tf32
        }
        __syncthreads();
        if (tid == 0) red_release(cnt);
        p ^= 1;
    }

    // ---- final loss: h(511) (tf32), gt[511]
    if (tid == 0) {
        while (ld_acq(cnt) < (unsigned)STEPS * 16u) __nanosleep(20);
    }
    __syncthreads();
    if (tid < 32) {
        const float* hr = g_h[p] + (B0 + cu) * HID;
        float s = 0.0f;
        #pragma unroll
        for (int q = 0; q < 8; ++q) {
            int k = lane + 32 * q;
            s += __ldcg(hr + k) * sWd[k];
        }
        #pragma unroll
        for (int sft = 16; sft > 0; sft >>= 1)
            s += __shfl_down_sync(0xffffffffu, s, sft);
        if (lane == 0) {
            float l = s + bdec;
            float g = gt[(size_t)STEPS * BATCH + B0 + cu];
            loss_local += fmaxf(l, 0.0f) + log1pf(__expf(-fabsf(l))) - g * l;
        }
    }
    if (tid == 0 || (wid == 3 && lane == 0)) atomicAdd(out, loss_local);
}

extern "C" void kernel_launch(void* const* d_in, const int* in_sizes, int n_in,
                              void* d_out, int out_size) {
    const float* x     = (const float*)d_in[0];
    const float* gt    = (const float*)d_in[1];
    const float* W_ih  = (const float*)d_in[2];
    const float* W_hh  = (const float*)d_in[3];
    const float* b_ih  = (const float*)d_in[4];
    const float* b_hh  = (const float*)d_in[5];
    const float* W_dec = (const float*)d_in[6];
    const float* b_dec = (const float*)d_in[7];
    float* out = (float*)d_out;

    cudaFuncSetAttribute(gru_main_kernel,
                         cudaFuncAttributeMaxDynamicSharedMemorySize, SMEM_BYTES);

    gru_init_kernel<<<1024, 256>>>(out, x);
    gru_main_kernel<<<NCTA, NTHREADS, SMEM_BYTES>>>(
        x, gt, W_ih, W_hh, b_ih, b_hh, W_dec, b_dec, out);
}